// round 4
// baseline (speedup 1.0000x reference)
#include <cuda_runtime.h>
#include <cstdint>

#define T_LEN 4096
#define HDIM 256
#define NTAG 32
#define NEGV (-10000.0f)

// ---------------- scratch (no cudaMalloc allowed) ----------------
__device__ float g_xg[2][T_LEN][1024];   // input projections (+biases), fwd/bwd
__device__ float g_h[2][T_LEN][HDIM];    // LSTM hidden outputs, fwd/bwd
__device__ float g_feats[T_LEN][NTAG];   // CRF emission features
__device__ float g_WoutT[512][NTAG];     // W_out transposed
__device__ float g_fvh[T_LEN][NTAG];     // viterbi fv history (fv_{t-1} at step t)
__device__ unsigned char g_bp[T_LEN][NTAG]; // recomputed backpointers
__device__ int g_best;                   // terminal argmax tag

// ---------------- helpers ----------------
__device__ __forceinline__ void ffma2(unsigned long long &d, unsigned long long a,
                                      unsigned long long b) {
    asm("fma.rn.f32x2 %0, %1, %2, %0;" : "+l"(d) : "l"(a), "l"(b));
}
__device__ __forceinline__ unsigned smem_u32(const void* p) {
    return (unsigned)__cvta_generic_to_shared(p);
}
__device__ __forceinline__ unsigned mapa_cluster(unsigned addr, unsigned rank) {
    unsigned ra;
    asm("mapa.shared::cluster.u32 %0, %1, %2;" : "=r"(ra) : "r"(addr), "r"(rank));
    return ra;
}
__device__ __forceinline__ void st_cluster_f32(unsigned ra, float v) {
    asm volatile("st.shared::cluster.f32 [%0], %1;" :: "r"(ra), "f"(v) : "memory");
}
__device__ __forceinline__ void st_release_cluster_u32(unsigned ra, unsigned v) {
    asm volatile("st.release.cluster.shared::cluster.u32 [%0], %1;" :: "r"(ra), "r"(v) : "memory");
}
__device__ __forceinline__ unsigned ld_vol_shared_u32(unsigned a) {
    unsigned v;
    asm volatile("ld.volatile.shared.u32 %0, [%1];" : "=r"(v) : "r"(a));
    return v;
}
__device__ __forceinline__ void cluster_sync_() {
    asm volatile("barrier.cluster.arrive.aligned;\n\tbarrier.cluster.wait.aligned;" ::: "memory");
}

// ================= 1) xg GEMM: (T x 256) @ (256 x 2048) + bias =================
__global__ void __launch_bounds__(256) xg_gemm_kernel(
    const int* __restrict__ seq, const float* __restrict__ E,
    const float* __restrict__ Wih_f, const float* __restrict__ bih_f, const float* __restrict__ bhh_f,
    const float* __restrict__ Wih_b, const float* __restrict__ bih_b, const float* __restrict__ bhh_b)
{
    __shared__ float As[64][17];                 // [t][k], padded
    __shared__ __align__(16) float Bs[16][68];   // [k][n], 16B-aligned rows

    const int tid = threadIdx.x;
    const int t0  = blockIdx.x * 64;
    const int n0  = blockIdx.y * 64;           // tile never straddles directions
    const int dir = n0 >> 10;
    const int gr0 = n0 & 1023;
    const float* __restrict__ W = dir ? Wih_b : Wih_f;

    const int lr = tid >> 2;                   // load row 0..63
    const int lq = tid & 3;                    // float4 slot within k-tile
    const long arow = (long)__ldg(seq + t0 + lr) * 256;
    const long brow = (long)(gr0 + lr) * 256;

    const int tx = tid & 15, ty = tid >> 4;
    float acc[4][4];
#pragma unroll
    for (int i = 0; i < 4; ++i)
#pragma unroll
        for (int j = 0; j < 4; ++j) acc[i][j] = 0.f;

    for (int kt = 0; kt < 256; kt += 16) {
        float4 a4 = *(const float4*)(E + arow + kt + lq * 4);
        float4 b4 = *(const float4*)(W + brow + kt + lq * 4);
        __syncthreads();
        As[lr][lq*4+0] = a4.x; As[lr][lq*4+1] = a4.y;
        As[lr][lq*4+2] = a4.z; As[lr][lq*4+3] = a4.w;
        Bs[lq*4+0][lr] = b4.x; Bs[lq*4+1][lr] = b4.y;
        Bs[lq*4+2][lr] = b4.z; Bs[lq*4+3][lr] = b4.w;
        __syncthreads();
#pragma unroll
        for (int k = 0; k < 16; ++k) {
            float av[4];
#pragma unroll
            for (int i = 0; i < 4; ++i) av[i] = As[ty*4+i][k];
            float4 bv = *(const float4*)&Bs[k][tx*4];
#pragma unroll
            for (int i = 0; i < 4; ++i) {
                acc[i][0] += av[i] * bv.x;
                acc[i][1] += av[i] * bv.y;
                acc[i][2] += av[i] * bv.z;
                acc[i][3] += av[i] * bv.w;
            }
        }
    }

    const float* bi = dir ? bih_b : bih_f;
    const float* bh = dir ? bhh_b : bhh_f;
    float bias[4];
#pragma unroll
    for (int j = 0; j < 4; ++j)
        bias[j] = __ldg(bi + gr0 + tx*4 + j) + __ldg(bh + gr0 + tx*4 + j);
#pragma unroll
    for (int i = 0; i < 4; ++i) {
        float* op = &g_xg[dir][t0 + ty*4 + i][gr0 + tx*4];
#pragma unroll
        for (int j = 0; j < 4; ++j) op[j] = acc[i][j] + bias[j];
    }
}

// ================= 2) LSTM recurrence: one 8-CTA cluster per direction =================
// CTA r owns h rows [r*32, r*32+32) -> 128 gate rows; Whh slice register-resident.
// 8 warps: warp w -> gate q = w&3, k-half kh = w>>2; lane = h-row within slice.
// Sync per step: pair barrier (q, q+4) -> act in warps 0-3 -> bar 1 (warps 0-3)
// -> warp 0 cell update, DSMEM h broadcast, per-rank monotone release flag.
// Consumers spin on 8 local flags then fence.acq_rel.cluster.
__global__ void __cluster_dims__(8,1,1) __launch_bounds__(256,1)
lstm_kernel(const float* __restrict__ Whh_f, const float* __restrict__ Whh_b,
            const float* __restrict__ h0, const float* __restrict__ c0)
{
    __shared__ __align__(16) float h_buf[2][HDIM];
    __shared__ float red[8][32];
    __shared__ unsigned flags[8];

    const int tid = threadIdx.x;
    const int w = tid >> 5, l = tid & 31;
    const int r   = blockIdx.x;    // cluster rank (cluster spans x)
    const int dir = blockIdx.y;
    const int q = w & 3, kh = w >> 2;
    const int row = q * 256 + r * 32 + l;
    const float* __restrict__ Whh = dir ? Whh_b : Whh_f;
    const unsigned long long* wp =
        (const unsigned long long*)(Whh + (long)row * 256 + kh * 128);

    unsigned long long w2[64];                 // 128 weights packed as f32x2 pairs
#pragma unroll
    for (int m = 0; m < 64; ++m) w2[m] = __ldg(wp + m);

    if (tid < 8) flags[tid] = 0;
    h_buf[0][tid] = __ldg(h0 + dir * HDIM + tid);
    float c = 0.f;
    if (w == 0) c = __ldg(c0 + dir * HDIM + r * 32 + l);

    // Precompute remote addresses (loop-invariant mapa)
    unsigned ra_h[2][8], ra_flag;
    {
        unsigned a0 = smem_u32(&h_buf[0][r * 32 + l]);
        unsigned a1 = smem_u32(&h_buf[1][r * 32 + l]);
#pragma unroll
        for (int rr = 0; rr < 8; ++rr) {
            ra_h[0][rr] = mapa_cluster(a0, (unsigned)rr);
            ra_h[1][rr] = mapa_cluster(a1, (unsigned)rr);
        }
        ra_flag = mapa_cluster(smem_u32(&flags[r]), (unsigned)(l & 7));
    }
    const unsigned flags_base = smem_u32(&flags[0]);

    __syncthreads();
    cluster_sync_();                           // all CTAs initialized before remote stores

    const float* __restrict__ xg = &g_xg[dir][0][0];
    float* __restrict__ hout = &g_h[dir][0][0];

    // prefetch step-0 input projection
    float xg_pre = 0.f;
    if (kh == 0) xg_pre = __ldg(xg + (dir ? (T_LEN - 1) : 0) * 1024 + row);

    int p = 0;
    for (int step = 0; step < T_LEN; ++step) {
        if (step) {                                      // wait for all 8 producers
            const unsigned need = (unsigned)step;
            for (;;) {
                bool ok = true;
#pragma unroll
                for (int rr = 0; rr < 8; ++rr)
                    ok &= (ld_vol_shared_u32(flags_base + 4u * rr) >= need);
                if (ok) break;
            }
            asm volatile("fence.acq_rel.cluster;" ::: "memory");
        }

        const float xgv = xg_pre;
        if (kh == 0 && step + 1 < T_LEN) {               // prefetch next step under the dot
            const int tn = dir ? (T_LEN - 2 - step) : (step + 1);
            xg_pre = __ldg(xg + tn * 1024 + row);
        }

        unsigned long long a0 = 0ull, a1 = 0ull;
        const ulonglong2* hp = (const ulonglong2*)&h_buf[p][kh * 128];
#pragma unroll
        for (int kk = 0; kk < 32; ++kk) {
            ulonglong2 hv = hp[kk];                       // LDS.128, warp-uniform broadcast
            ffma2(a0, w2[2*kk],   hv.x);
            ffma2(a1, w2[2*kk+1], hv.y);
        }
        float dot = __uint_as_float((unsigned)a0) + __uint_as_float((unsigned)(a0 >> 32))
                  + __uint_as_float((unsigned)a1) + __uint_as_float((unsigned)(a1 >> 32));
        red[w][l] = dot;
        // pair barrier: warp q with warp q+4 (64 threads), IDs 2..5
        asm volatile("bar.sync %0, 64;" :: "r"(2 + q) : "memory");

        if (kh == 0) {                                   // warps 0..3: combine + activation
            float s = red[w][l] + red[w + 4][l] + xgv;
            red[w][l] = (q == 2) ? tanhf(s) : (1.f / (1.f + expf(-s)));
            asm volatile("bar.sync 1, 128;" ::: "memory");   // warps 0-3
            if (w == 0) {                                // warp 0: cell + broadcast + release
                float iv = red[0][l], fvl = red[1][l], gv = red[2][l], ov = red[3][l];
                c = fvl * c + iv * gv;
                float hnew = ov * tanhf(c);
                if (step < T_LEN - 1) {
                    const int b = p ^ 1;
#pragma unroll
                    for (int rr = 0; rr < 8; ++rr)
                        st_cluster_f32(ra_h[b][rr], hnew);
                    __syncwarp();                        // all lanes' stores before release
                    if (l < 8)
                        st_release_cluster_u32(ra_flag, (unsigned)(step + 1));
                }
                const int t = dir ? (T_LEN - 1 - step) : step;
                hout[(long)t * HDIM + r * 32 + l] = hnew;   // off the critical path
            }
        }
        p ^= 1;
    }
}

// ================= 3) W_out transpose + feats =================
__global__ void prep_woutT_kernel(const float* __restrict__ W_out) {
    int i = blockIdx.x * 256 + threadIdx.x;
    if (i < NTAG * 512) {
        int n = i >> 9, k = i & 511;
        g_WoutT[k][n] = W_out[i];
    }
}

__global__ void __launch_bounds__(256) feats_kernel(const float* __restrict__ b_out) {
    const int wi = threadIdx.x >> 5, n = threadIdx.x & 31;
    const int t = blockIdx.x * 8 + wi;
    const float* __restrict__ hf = &g_h[0][t][0];
    const float* __restrict__ hb = &g_h[1][t][0];
    float acc = 0.f;
#pragma unroll 8
    for (int k = 0; k < 256; ++k) acc += hf[k] * g_WoutT[k][n];
#pragma unroll 8
    for (int k = 0; k < 256; ++k) acc += hb[k] * g_WoutT[256 + k][n];
    g_feats[t][n] = acc + __ldg(b_out + n);
}

// ================= 4a) Viterbi forward: max-only (FMNMX tree), stream fv history =====
__global__ void viterbi_fwd_kernel(const float* __restrict__ trans, float* __restrict__ out,
                                   int out_size) {
    __shared__ __align__(16) float fv[NTAG];
    const int n = threadIdx.x;

    float trow[NTAG];
#pragma unroll
    for (int p = 0; p < NTAG; ++p) trow[p] = __ldg(trans + n * NTAG + p);

    float myfv = (n == 30) ? 0.f : NEGV;                 // START = 30
    fv[n] = myfv;
    __syncwarp();

    const float4* fvv = (const float4*)fv;
    float feat = __ldg(&g_feats[0][n]);                  // prefetched emission
    for (int t = 0; t < T_LEN; ++t) {
        g_fvh[t][n] = myfv;                              // fv_{t-1} history (coalesced)
        float feat_nx = (t + 1 < T_LEN) ? __ldg(&g_feats[t + 1][n]) : 0.f;
        float v[NTAG];
#pragma unroll
        for (int j = 0; j < 8; ++j) {
            float4 f4 = fvv[j];
            v[j*4+0] = f4.x + trow[j*4+0];
            v[j*4+1] = f4.y + trow[j*4+1];
            v[j*4+2] = f4.z + trow[j*4+2];
            v[j*4+3] = f4.w + trow[j*4+3];
        }
#pragma unroll
        for (int off = 16; off >= 1; off >>= 1)
#pragma unroll
            for (int i = 0; i < 16; ++i)
                if (i < off) v[i] = fmaxf(v[i], v[i + off]);
        myfv = v[0] + feat;
        feat = feat_nx;
        __syncwarp();
        fv[n] = myfv;
        __syncwarp();
    }

    float term = myfv + __ldg(trans + 31 * NTAG + n);    // STOP = 31 row
    float bv = term; int bi = n;
#pragma unroll
    for (int off = 16; off; off >>= 1) {
        float ov = __shfl_down_sync(0xffffffffu, bv, off);
        int   oi = __shfl_down_sync(0xffffffffu, bi, off);
        if (ov > bv || (ov == bv && oi < bi)) { bv = ov; bi = oi; }
    }
    if (n == 0) {
        g_best = bi;
        if (out_size > T_LEN || out_size == 1) out[0] = bv;   // score slot
    }
}

// ================= 4b) Backpointer recompute (parallel, bitwise-identical FADDs) =====
__global__ void __launch_bounds__(256) bp_kernel(const float* __restrict__ trans) {
    const int idx = blockIdx.x * 256 + threadIdx.x;      // t uniform per warp, n = lane
    const int t = idx >> 5, n = idx & 31;
    const float* __restrict__ fvp = &g_fvh[t][0];
    const float* __restrict__ tr  = trans + n * NTAG;
    float m = -1e30f; int b = 0;
#pragma unroll
    for (int p = 0; p < NTAG; ++p) {
        float v = __ldg(fvp + p) + __ldg(tr + p);        // same FADD operands as forward
        if (v > m) { m = v; b = p; }                     // strict > == first-index argmax
    }
    g_bp[t][n] = (unsigned char)b;
}

// ================= 4c) Backtrace: bp table in smem, then parallel path write =========
__global__ void backtrace_kernel(float* __restrict__ out, int out_size) {
    extern __shared__ unsigned char dyn[];               // [0,128K): bp, [128K,+16K): path
    int* path = (int*)(dyn + T_LEN * NTAG);
    const int tid = threadIdx.x;

    const int4* src = (const int4*)&g_bp[0][0];
    int4* dst = (int4*)dyn;
    for (int i = tid; i < T_LEN * NTAG / 16; i += blockDim.x) dst[i] = src[i];
    __syncthreads();

    if (tid == 0) {
        int b = g_best;
        path[T_LEN - 1] = b;
        for (int t = T_LEN - 1; t >= 1; --t) {
            b = dyn[t * NTAG + b];
            path[t - 1] = b;
        }
    }
    __syncthreads();

    if (out_size >= T_LEN) {
        int base = out_size - T_LEN;
        for (int i = tid; i < T_LEN; i += blockDim.x)
            out[base + i] = (float)path[i];
    }
}

// ================= launch =================
extern "C" void kernel_launch(void* const* d_in, const int* in_sizes, int n_in,
                              void* d_out, int out_size) {
    const int*   seq   = (const int*)  d_in[0];
    const float* E     = (const float*)d_in[1];
    const float* Wih_f = (const float*)d_in[2];
    const float* Whh_f = (const float*)d_in[3];
    const float* bih_f = (const float*)d_in[4];
    const float* bhh_f = (const float*)d_in[5];
    const float* Wih_b = (const float*)d_in[6];
    const float* Whh_b = (const float*)d_in[7];
    const float* bih_b = (const float*)d_in[8];
    const float* bhh_b = (const float*)d_in[9];
    const float* h0    = (const float*)d_in[10];
    const float* c0    = (const float*)d_in[11];
    const float* W_out = (const float*)d_in[12];
    const float* b_out = (const float*)d_in[13];
    const float* trans = (const float*)d_in[14];
    float* out = (float*)d_out;

    cudaFuncSetAttribute(backtrace_kernel,
                         cudaFuncAttributeMaxDynamicSharedMemorySize,
                         T_LEN * NTAG + T_LEN * (int)sizeof(int));

    xg_gemm_kernel<<<dim3(64, 32), 256>>>(seq, E, Wih_f, bih_f, bhh_f,
                                          Wih_b, bih_b, bhh_b);
    prep_woutT_kernel<<<64, 256>>>(W_out);
    lstm_kernel<<<dim3(8, 2), 256>>>(Whh_f, Whh_b, h0, c0);
    feats_kernel<<<T_LEN / 8, 256>>>(b_out);
    viterbi_fwd_kernel<<<1, 32>>>(trans, out, out_size);
    bp_kernel<<<T_LEN * NTAG / 256, 256>>>(trans);
    backtrace_kernel<<<1, 128, T_LEN * NTAG + T_LEN * (int)sizeof(int)>>>(out, out_size);
}

// round 7
// speedup vs baseline: 1.1898x; 1.1898x over previous
#include <cuda_runtime.h>
#include <cstdint>

#define T_LEN 4096
#define HDIM 256
#define NTAG 32
#define NEGV (-10000.0f)

// ---------------- scratch (no cudaMalloc allowed) ----------------
__device__ float g_xg[2][T_LEN][1024];   // input projections (+biases), fwd/bwd
__device__ float g_h[2][T_LEN][HDIM];    // LSTM hidden outputs, fwd/bwd
__device__ float g_feats[T_LEN][NTAG];   // CRF emission features
__device__ float g_WoutT[512][NTAG];     // W_out transposed
__device__ float g_fvh[T_LEN][NTAG];     // viterbi fv history (fv_{t-1} at step t)
__device__ unsigned char g_bp[T_LEN][NTAG]; // recomputed backpointers
__device__ int g_best;                   // terminal argmax tag

// ---------------- helpers ----------------
__device__ __forceinline__ void ffma2(unsigned long long &d, unsigned long long a,
                                      unsigned long long b) {
    asm("fma.rn.f32x2 %0, %1, %2, %0;" : "+l"(d) : "l"(a), "l"(b));
}
__device__ __forceinline__ unsigned smem_u32(const void* p) {
    return (unsigned)__cvta_generic_to_shared(p);
}
__device__ __forceinline__ unsigned mapa_cluster(unsigned addr, unsigned rank) {
    unsigned ra;
    asm("mapa.shared::cluster.u32 %0, %1, %2;" : "=r"(ra) : "r"(addr), "r"(rank));
    return ra;
}
__device__ __forceinline__ void st_cluster_f32(unsigned ra, float v) {
    asm volatile("st.shared::cluster.f32 [%0], %1;" :: "r"(ra), "f"(v) : "memory");
}
__device__ __forceinline__ void mbar_init(unsigned addr, unsigned count) {
    asm volatile("mbarrier.init.shared.b64 [%0], %1;" :: "r"(addr), "r"(count) : "memory");
}
__device__ __forceinline__ void mbar_arrive_remote(unsigned ra) {
    asm volatile("mbarrier.arrive.release.cluster.shared::cluster.b64 _, [%0];"
                 :: "r"(ra) : "memory");
}
__device__ __forceinline__ void mbar_wait_cluster(unsigned addr, unsigned parity) {
    asm volatile(
        "{\n\t"
        ".reg .pred P;\n\t"
        "WAIT_%=:\n\t"
        "mbarrier.try_wait.parity.acquire.cluster.shared::cta.b64 P, [%0], %1, 0x989680;\n\t"
        "@P bra.uni DONE_%=;\n\t"
        "bra.uni WAIT_%=;\n\t"
        "DONE_%=:\n\t"
        "}"
        :: "r"(addr), "r"(parity) : "memory");
}
__device__ __forceinline__ void cluster_sync_() {
    asm volatile("barrier.cluster.arrive.aligned;\n\tbarrier.cluster.wait.aligned;" ::: "memory");
}

// ================= 1) xg GEMM: (T x 256) @ (256 x 2048) + bias =================
__global__ void __launch_bounds__(256) xg_gemm_kernel(
    const int* __restrict__ seq, const float* __restrict__ E,
    const float* __restrict__ Wih_f, const float* __restrict__ bih_f, const float* __restrict__ bhh_f,
    const float* __restrict__ Wih_b, const float* __restrict__ bih_b, const float* __restrict__ bhh_b)
{
    __shared__ float As[64][17];                 // [t][k], padded
    __shared__ __align__(16) float Bs[16][68];   // [k][n], 16B-aligned rows

    const int tid = threadIdx.x;
    const int t0  = blockIdx.x * 64;
    const int n0  = blockIdx.y * 64;           // tile never straddles directions
    const int dir = n0 >> 10;
    const int gr0 = n0 & 1023;
    const float* __restrict__ W = dir ? Wih_b : Wih_f;

    const int lr = tid >> 2;                   // load row 0..63
    const int lq = tid & 3;                    // float4 slot within k-tile
    const long arow = (long)__ldg(seq + t0 + lr) * 256;
    const long brow = (long)(gr0 + lr) * 256;

    const int tx = tid & 15, ty = tid >> 4;
    float acc[4][4];
#pragma unroll
    for (int i = 0; i < 4; ++i)
#pragma unroll
        for (int j = 0; j < 4; ++j) acc[i][j] = 0.f;

    for (int kt = 0; kt < 256; kt += 16) {
        float4 a4 = *(const float4*)(E + arow + kt + lq * 4);
        float4 b4 = *(const float4*)(W + brow + kt + lq * 4);
        __syncthreads();
        As[lr][lq*4+0] = a4.x; As[lr][lq*4+1] = a4.y;
        As[lr][lq*4+2] = a4.z; As[lr][lq*4+3] = a4.w;
        Bs[lq*4+0][lr] = b4.x; Bs[lq*4+1][lr] = b4.y;
        Bs[lq*4+2][lr] = b4.z; Bs[lq*4+3][lr] = b4.w;
        __syncthreads();
#pragma unroll
        for (int k = 0; k < 16; ++k) {
            float av[4];
#pragma unroll
            for (int i = 0; i < 4; ++i) av[i] = As[ty*4+i][k];
            float4 bv = *(const float4*)&Bs[k][tx*4];
#pragma unroll
            for (int i = 0; i < 4; ++i) {
                acc[i][0] += av[i] * bv.x;
                acc[i][1] += av[i] * bv.y;
                acc[i][2] += av[i] * bv.z;
                acc[i][3] += av[i] * bv.w;
            }
        }
    }

    const float* bi = dir ? bih_b : bih_f;
    const float* bh = dir ? bhh_b : bhh_f;
    float bias[4];
#pragma unroll
    for (int j = 0; j < 4; ++j)
        bias[j] = __ldg(bi + gr0 + tx*4 + j) + __ldg(bh + gr0 + tx*4 + j);
#pragma unroll
    for (int i = 0; i < 4; ++i) {
        float* op = &g_xg[dir][t0 + ty*4 + i][gr0 + tx*4];
#pragma unroll
        for (int j = 0; j < 4; ++j) op[j] = acc[i][j] + bias[j];
    }
}

// ================= 2) LSTM recurrence: one 8-CTA cluster per direction =================
// CTA r owns h rows [r*32, r*32+32) -> 128 gate rows; Whh slice register-resident.
// 8 warps: warp w -> gate q = w&3, k-half kh = w>>2; lane = h-row within slice.
// Sync: two alternating mbarriers per CTA (expect 8 arrivals = one per producer CTA).
// Producer warp 0: DSMEM h stores -> syncwarp -> lanes 0-7 remote mbarrier.arrive
// (release.cluster). Consumers: try_wait.parity.acquire.cluster (HW sleep).
__global__ void __cluster_dims__(8,1,1) __launch_bounds__(256,1)
lstm_kernel(const float* __restrict__ Whh_f, const float* __restrict__ Whh_b,
            const float* __restrict__ h0, const float* __restrict__ c0)
{
    __shared__ __align__(16) float h_buf[2][HDIM];
    __shared__ float red[8][32];
    __shared__ __align__(8) unsigned long long mbar[2];

    const int tid = threadIdx.x;
    const int w = tid >> 5, l = tid & 31;
    const int r   = blockIdx.x;    // cluster rank (cluster spans x)
    const int dir = blockIdx.y;
    const int q = w & 3, kh = w >> 2;
    const int row = q * 256 + r * 32 + l;
    const float* __restrict__ Whh = dir ? Whh_b : Whh_f;
    const unsigned long long* wp =
        (const unsigned long long*)(Whh + (long)row * 256 + kh * 128);

    unsigned long long w2[64];                 // 128 weights packed as f32x2 pairs
#pragma unroll
    for (int m = 0; m < 64; ++m) w2[m] = __ldg(wp + m);

    if (tid == 0) {
        mbar_init(smem_u32(&mbar[0]), 8);
        mbar_init(smem_u32(&mbar[1]), 8);
    }
    h_buf[0][tid] = __ldg(h0 + dir * HDIM + tid);
    float c = 0.f;
    if (w == 0) c = __ldg(c0 + dir * HDIM + r * 32 + l);

    // Precompute remote addresses (loop-invariant mapa)
    unsigned ra_h[2][8], ra_mb[2];
    {
        unsigned a0 = smem_u32(&h_buf[0][r * 32 + l]);
        unsigned a1 = smem_u32(&h_buf[1][r * 32 + l]);
#pragma unroll
        for (int rr = 0; rr < 8; ++rr) {
            ra_h[0][rr] = mapa_cluster(a0, (unsigned)rr);
            ra_h[1][rr] = mapa_cluster(a1, (unsigned)rr);
        }
        // lane l (<8) arrives on rank l's mbarriers
        ra_mb[0] = mapa_cluster(smem_u32(&mbar[0]), (unsigned)(l & 7));
        ra_mb[1] = mapa_cluster(smem_u32(&mbar[1]), (unsigned)(l & 7));
    }
    const unsigned mb_local[2] = { smem_u32(&mbar[0]), smem_u32(&mbar[1]) };

    __syncthreads();
    cluster_sync_();                           // all mbarriers initialized cluster-wide

    const float* __restrict__ xg = &g_xg[dir][0][0];
    float* __restrict__ hout = &g_h[dir][0][0];

    // prefetch step-0 input projection
    float xg_pre = 0.f;
    if (kh == 0) xg_pre = __ldg(xg + (dir ? (T_LEN - 1) : 0) * 1024 + row);

    unsigned ph0 = 0, ph1 = 0;                 // per-buffer phase parity
    int p = 0;
    for (int step = 0; step < T_LEN; ++step) {
        if (step) {                                      // wait for all 8 producers
            if (step & 1) { mbar_wait_cluster(mb_local[1], ph1); ph1 ^= 1u; }
            else          { mbar_wait_cluster(mb_local[0], ph0); ph0 ^= 1u; }
        }

        const float xgv = xg_pre;
        if (kh == 0 && step + 1 < T_LEN) {               // prefetch next step under the dot
            const int tn = dir ? (T_LEN - 2 - step) : (step + 1);
            xg_pre = __ldg(xg + tn * 1024 + row);
        }

        unsigned long long a0 = 0ull, a1 = 0ull;
        const ulonglong2* hp = (const ulonglong2*)&h_buf[p][kh * 128];
#pragma unroll
        for (int kk = 0; kk < 32; ++kk) {
            ulonglong2 hv = hp[kk];                       // LDS.128, warp-uniform broadcast
            ffma2(a0, w2[2*kk],   hv.x);
            ffma2(a1, w2[2*kk+1], hv.y);
        }
        float dot = __uint_as_float((unsigned)a0) + __uint_as_float((unsigned)(a0 >> 32))
                  + __uint_as_float((unsigned)a1) + __uint_as_float((unsigned)(a1 >> 32));
        red[w][l] = dot;
        // pair barrier: warp q with warp q+4 (64 threads), IDs 2..5
        asm volatile("bar.sync %0, 64;" :: "r"(2 + q) : "memory");

        if (kh == 0) {                                   // warps 0..3: combine + activation
            float s = red[w][l] + red[w + 4][l] + xgv;
            red[w][l] = (q == 2) ? tanhf(s) : (1.f / (1.f + expf(-s)));
            asm volatile("bar.sync 1, 128;" ::: "memory");   // warps 0-3
            if (w == 0) {                                // warp 0: cell + broadcast + arrive
                float iv = red[0][l], fvl = red[1][l], gv = red[2][l], ov = red[3][l];
                c = fvl * c + iv * gv;
                float hnew = ov * tanhf(c);
                if (step < T_LEN - 1) {
                    const int b = p ^ 1;
#pragma unroll
                    for (int rr = 0; rr < 8; ++rr)
                        st_cluster_f32(ra_h[b][rr], hnew);
                    __syncwarp();                        // all lanes' stores before arrive
                    if (l < 8)
                        mbar_arrive_remote(ra_mb[(step + 1) & 1]);
                }
                const int t = dir ? (T_LEN - 1 - step) : step;
                hout[(long)t * HDIM + r * 32 + l] = hnew;   // off the critical path
            }
        }
        p ^= 1;
    }
    cluster_sync_();                           // clean teardown (no in-flight remote ops)
}

// ================= 3) W_out transpose + feats =================
__global__ void prep_woutT_kernel(const float* __restrict__ W_out) {
    int i = blockIdx.x * 256 + threadIdx.x;
    if (i < NTAG * 512) {
        int n = i >> 9, k = i & 511;
        g_WoutT[k][n] = W_out[i];
    }
}

__global__ void __launch_bounds__(256) feats_kernel(const float* __restrict__ b_out) {
    const int wi = threadIdx.x >> 5, n = threadIdx.x & 31;
    const int t = blockIdx.x * 8 + wi;
    const float* __restrict__ hf = &g_h[0][t][0];
    const float* __restrict__ hb = &g_h[1][t][0];
    float acc = 0.f;
#pragma unroll 8
    for (int k = 0; k < 256; ++k) acc += hf[k] * g_WoutT[k][n];
#pragma unroll 8
    for (int k = 0; k < 256; ++k) acc += hb[k] * g_WoutT[256 + k][n];
    g_feats[t][n] = acc + __ldg(b_out + n);
}

// ================= 4a) Viterbi forward: max-only (FMNMX tree), stream fv history =====
__global__ void viterbi_fwd_kernel(const float* __restrict__ trans, float* __restrict__ out,
                                   int out_size) {
    __shared__ __align__(16) float fv[NTAG];
    const int n = threadIdx.x;

    float trow[NTAG];
#pragma unroll
    for (int p = 0; p < NTAG; ++p) trow[p] = __ldg(trans + n * NTAG + p);

    float myfv = (n == 30) ? 0.f : NEGV;                 // START = 30
    fv[n] = myfv;
    __syncwarp();

    const float4* fvv = (const float4*)fv;
    float feat = __ldg(&g_feats[0][n]);                  // prefetched emission
    for (int t = 0; t < T_LEN; ++t) {
        g_fvh[t][n] = myfv;                              // fv_{t-1} history (coalesced)
        float feat_nx = (t + 1 < T_LEN) ? __ldg(&g_feats[t + 1][n]) : 0.f;
        float v[NTAG];
#pragma unroll
        for (int j = 0; j < 8; ++j) {
            float4 f4 = fvv[j];
            v[j*4+0] = f4.x + trow[j*4+0];
            v[j*4+1] = f4.y + trow[j*4+1];
            v[j*4+2] = f4.z + trow[j*4+2];
            v[j*4+3] = f4.w + trow[j*4+3];
        }
#pragma unroll
        for (int off = 16; off >= 1; off >>= 1)
#pragma unroll
            for (int i = 0; i < 16; ++i)
                if (i < off) v[i] = fmaxf(v[i], v[i + off]);
        myfv = v[0] + feat;
        feat = feat_nx;
        __syncwarp();
        fv[n] = myfv;
        __syncwarp();
    }

    float term = myfv + __ldg(trans + 31 * NTAG + n);    // STOP = 31 row
    float bv = term; int bi = n;
#pragma unroll
    for (int off = 16; off; off >>= 1) {
        float ov = __shfl_down_sync(0xffffffffu, bv, off);
        int   oi = __shfl_down_sync(0xffffffffu, bi, off);
        if (ov > bv || (ov == bv && oi < bi)) { bv = ov; bi = oi; }
    }
    if (n == 0) {
        g_best = bi;
        if (out_size > T_LEN || out_size == 1) out[0] = bv;   // score slot
    }
}

// ================= 4b) Backpointer recompute (parallel, bitwise-identical FADDs) =====
__global__ void __launch_bounds__(256) bp_kernel(const float* __restrict__ trans) {
    const int idx = blockIdx.x * 256 + threadIdx.x;      // t uniform per warp, n = lane
    const int t = idx >> 5, n = idx & 31;
    const float* __restrict__ fvp = &g_fvh[t][0];
    const float* __restrict__ tr  = trans + n * NTAG;
    float m = -1e30f; int b = 0;
#pragma unroll
    for (int p = 0; p < NTAG; ++p) {
        float v = __ldg(fvp + p) + __ldg(tr + p);        // same FADD operands as forward
        if (v > m) { m = v; b = p; }                     // strict > == first-index argmax
    }
    g_bp[t][n] = (unsigned char)b;
}

// ================= 4c) Backtrace: bp table in smem, then parallel path write =========
__global__ void backtrace_kernel(float* __restrict__ out, int out_size) {
    extern __shared__ unsigned char dyn[];               // [0,128K): bp, [128K,+16K): path
    int* path = (int*)(dyn + T_LEN * NTAG);
    const int tid = threadIdx.x;

    const int4* src = (const int4*)&g_bp[0][0];
    int4* dst = (int4*)dyn;
    for (int i = tid; i < T_LEN * NTAG / 16; i += blockDim.x) dst[i] = src[i];
    __syncthreads();

    if (tid == 0) {
        int b = g_best;
        path[T_LEN - 1] = b;
        for (int t = T_LEN - 1; t >= 1; --t) {
            b = dyn[t * NTAG + b];
            path[t - 1] = b;
        }
    }
    __syncthreads();

    if (out_size >= T_LEN) {
        int base = out_size - T_LEN;
        for (int i = tid; i < T_LEN; i += blockDim.x)
            out[base + i] = (float)path[i];
    }
}

// ================= launch =================
extern "C" void kernel_launch(void* const* d_in, const int* in_sizes, int n_in,
                              void* d_out, int out_size) {
    const int*   seq   = (const int*)  d_in[0];
    const float* E     = (const float*)d_in[1];
    const float* Wih_f = (const float*)d_in[2];
    const float* Whh_f = (const float*)d_in[3];
    const float* bih_f = (const float*)d_in[4];
    const float* bhh_f = (const float*)d_in[5];
    const float* Wih_b = (const float*)d_in[6];
    const float* Whh_b = (const float*)d_in[7];
    const float* bih_b = (const float*)d_in[8];
    const float* bhh_b = (const float*)d_in[9];
    const float* h0    = (const float*)d_in[10];
    const float* c0    = (const float*)d_in[11];
    const float* W_out = (const float*)d_in[12];
    const float* b_out = (const float*)d_in[13];
    const float* trans = (const float*)d_in[14];
    float* out = (float*)d_out;

    cudaFuncSetAttribute(backtrace_kernel,
                         cudaFuncAttributeMaxDynamicSharedMemorySize,
                         T_LEN * NTAG + T_LEN * (int)sizeof(int));

    xg_gemm_kernel<<<dim3(64, 32), 256>>>(seq, E, Wih_f, bih_f, bhh_f,
                                          Wih_b, bih_b, bhh_b);
    prep_woutT_kernel<<<64, 256>>>(W_out);
    lstm_kernel<<<dim3(8, 2), 256>>>(Whh_f, Whh_b, h0, c0);
    feats_kernel<<<T_LEN / 8, 256>>>(b_out);
    viterbi_fwd_kernel<<<1, 32>>>(trans, out, out_size);
    bp_kernel<<<T_LEN * NTAG / 256, 256>>>(trans);
    backtrace_kernel<<<1, 128, T_LEN * NTAG + T_LEN * (int)sizeof(int)>>>(out, out_size);
}